// round 16
// baseline (speedup 1.0000x reference)
#include <cuda_runtime.h>
#include <cuda_fp16.h>
#include <math.h>

#define BB 2
#define TT 2048
#define CC 1024
#define HH 16
#define BT (BB*TT)   // 4096

typedef unsigned int u32;
typedef unsigned long long u64;

// ---------------------------------------------------------------------------
// Scratch (__device__ globals; no allocations allowed)
// ---------------------------------------------------------------------------
__device__ __align__(256) __half g_x[(size_t)BT * CC];
__device__ __align__(256) __half g_wq[(size_t)3 * CC * CC];
__device__ __align__(256) __half g_wp[(size_t)CC * CC];
__device__ __align__(256) __half g_qkv[(size_t)BT * 3 * CC];
__device__ __align__(256) __half g_att[(size_t)BT * CC];

// ---------------------------------------------------------------------------
// PTX helpers
// ---------------------------------------------------------------------------
__device__ __forceinline__ u32 s2u(const void* p) {
    u32 a;
    asm("{ .reg .u64 t; cvta.to.shared.u64 t, %1; cvt.u32.u64 %0, t; }"
        : "=r"(a) : "l"(p));
    return a;
}
__device__ __forceinline__ void cpa16(u32 dst, const void* src) {
    asm volatile("cp.async.cg.shared.global [%0], [%1], 16;" :: "r"(dst), "l"(src));
}
#define CP_COMMIT() asm volatile("cp.async.commit_group;" ::: "memory")
#define CP_WAIT0()  asm volatile("cp.async.wait_group 0;" ::: "memory")
__device__ __forceinline__ void ldsm4(u32* r, u32 addr) {
    asm volatile("ldmatrix.sync.aligned.m8n8.x4.shared.b16 {%0,%1,%2,%3}, [%4];"
                 : "=r"(r[0]), "=r"(r[1]), "=r"(r[2]), "=r"(r[3]) : "r"(addr));
}
__device__ __forceinline__ void ldsm4t(u32* r, u32 addr) {
    asm volatile("ldmatrix.sync.aligned.m8n8.x4.trans.shared.b16 {%0,%1,%2,%3}, [%4];"
                 : "=r"(r[0]), "=r"(r[1]), "=r"(r[2]), "=r"(r[3]) : "r"(addr));
}
__device__ __forceinline__ void mma16816(float* d, const u32* a, const u32* b) {
    asm volatile(
        "mma.sync.aligned.m16n8k16.row.col.f32.f16.f16.f32 "
        "{%0,%1,%2,%3}, {%4,%5,%6,%7}, {%8,%9}, {%0,%1,%2,%3};"
        : "+f"(d[0]), "+f"(d[1]), "+f"(d[2]), "+f"(d[3])
        : "r"(a[0]), "r"(a[1]), "r"(a[2]), "r"(a[3]), "r"(b[0]), "r"(b[1]));
}
// fp16-accumulate variant: D/C are two f16x2 regs {d0,d1}
__device__ __forceinline__ void mma16816h(u32* d, const u32* a, const u32* b) {
    asm volatile(
        "mma.sync.aligned.m16n8k16.row.col.f16.f16.f16.f16 "
        "{%0,%1}, {%2,%3,%4,%5}, {%6,%7}, {%0,%1};"
        : "+r"(d[0]), "+r"(d[1])
        : "r"(a[0]), "r"(a[1]), "r"(a[2]), "r"(a[3]), "r"(b[0]), "r"(b[1]));
}
__device__ __forceinline__ u32 pack2h(float a, float b) {
    u32 d;
    asm("cvt.rn.f16x2.f32 %0, %1, %2;" : "=r"(d) : "f"(b), "f"(a));
    return d;
}
// softplus with ONE MUFU: e = ex2(-|x|*log2e); z = 1+e in (1,2];
// ln(z) = ex*ln2 + p(m), where p is a deg-4 minimax poly for ln on [1,2)
// (FIXED from R15: poly gives natural log; combine is ex*ln2 + p, NOT
// (ex+p)*ln2).
__device__ __forceinline__ float softplus_f(float x) {
    float u = fminf(x, -x);                    // -|x|
    float e;
    asm("ex2.approx.f32 %0, %1;" : "=f"(e) : "f"(u * 1.4426950408889634f));
    float z = 1.f + e;                         // (1, 2]
    int i = __float_as_int(z);
    float ex = (float)((i >> 23) - 127);
    float m = __int_as_float((i & 0x007FFFFF) | 0x3F800000);
    float p = fmaf(m, -0.056570851f, 0.44717955f);   // p(m) ~= ln(m) on [1,2)
    p = fmaf(m, p, -1.4699568f);
    p = fmaf(m, p, 2.8212026f);
    p = fmaf(m, p, -1.7417939f);
    return fmaxf(x, 0.f) + fmaf(ex, 0.6931471805599453f, p);
}

// ---------------------------------------------------------------------------
// Fused fp32 -> fp16 rounding over the three inputs (one launch)
// ---------------------------------------------------------------------------
#define N4X (BT * CC / 4)           // 1,048,576
#define N4Q (3 * CC * CC / 4)       // 786,432
#define N4P (CC * CC / 4)           // 262,144
#define N4ALL (N4X + N4Q + N4P)

__global__ __launch_bounds__(256)
void round_all(const float4* __restrict__ x, const float4* __restrict__ wq,
               const float4* __restrict__ wp, uint2* __restrict__ dx,
               uint2* __restrict__ dwq, uint2* __restrict__ dwp) {
    int i = blockIdx.x * blockDim.x + threadIdx.x;
    const float4* s; uint2* d; int k;
    if (i < N4X)            { s = x;  d = dx;  k = i; }
    else if (i < N4X + N4Q) { s = wq; d = dwq; k = i - N4X; }
    else if (i < N4ALL)     { s = wp; d = dwp; k = i - N4X - N4Q; }
    else return;
    float4 v = s[k];
    d[k] = make_uint2(pack2h(v.x, v.y), pack2h(v.z, v.w));
}

// ---------------------------------------------------------------------------
// HMMA GEMM (fp16 in, fp32 accum): C[M,N] = A[M,K] @ W[N,K]^T
// 128x128x64 tile, 8 warps (2m x 4n), double buffer, ONE sync/iter, 2 CTAs/SM.
// Oh-path epilogue scales by `oscale` when bn < oscale_ncols (Q pre-scale).
// ---------------------------------------------------------------------------
#define GM_STAGE 32768
#define GM_SMEM_BYTES (2 * GM_STAGE)

__device__ __forceinline__ u32 sw8(int r, int c) {
    return (u32)(r * 128 + ((c ^ (r & 7)) << 4));
}

__device__ __forceinline__ void load_tile_g(
    u32 sbuf, int tid,
    const __half* __restrict__ A, const __half* __restrict__ W,
    int bm, int bn, int K, int k0)
{
    #pragma unroll
    for (int q = 0; q < 4; q++) {
        int idx = tid + q * 256;
        int r = idx >> 3;
        int c = idx & 7;
        u32 so = sw8(r, c);
        cpa16(sbuf +         so, A + (size_t)(bm + r) * K + k0 + c * 8);
        cpa16(sbuf + 16384 + so, W + (size_t)(bn + r) * K + k0 + c * 8);
    }
    CP_COMMIT();
}

__global__ __launch_bounds__(256, 2)
void gemm_mma(const __half* __restrict__ A, const __half* __restrict__ W,
              const float* __restrict__ bias, float* __restrict__ Cf,
              __half* __restrict__ Oh, int N, int K,
              float oscale, int oscale_ncols) {
    extern __shared__ char smem[];
    const u32 sb = s2u(smem);
    const int tid = threadIdx.x;
    const int wid = tid >> 5, lane = tid & 31;
    const int bm = blockIdx.y * 128, bn = blockIdx.x * 128;
    const int wm = (wid >> 2) * 64;
    const int wn = (wid & 3) * 32;

    float acc[4][4][4];
    #pragma unroll
    for (int i = 0; i < 4; i++)
        #pragma unroll
        for (int j = 0; j < 4; j++)
            #pragma unroll
            for (int u = 0; u < 4; u++) acc[i][j][u] = 0.f;

    const int NIT = K / 64;

    load_tile_g(sb, tid, A, W, bm, bn, K, 0);

    const int arow = lane & 15;
    const int akh  = lane >> 4;
    const int bj   = (lane >> 4) & 1;
    const int bkc  = (lane >> 3) & 1;
    const int brow = lane & 7;

    for (int it = 0; it < NIT; it++) {
        CP_WAIT0();
        __syncthreads();
        if (it + 1 < NIT) {
            load_tile_g(sb + ((it + 1) & 1) * GM_STAGE, tid,
                        A, W, bm, bn, K, (it + 1) * 64);
        }

        const u32 bb = sb + (it & 1) * GM_STAGE;
        #pragma unroll
        for (int kk2 = 0; kk2 < 8; kk2 += 2) {
            u32 ah[4][4];
            #pragma unroll
            for (int i = 0; i < 4; i++) {
                int row = wm + i * 16 + arow;
                ldsm4(ah[i], bb + sw8(row, kk2 + akh));
            }
            u32 wh4[2][4];
            #pragma unroll
            for (int jp = 0; jp < 2; jp++) {
                int row = wn + (jp * 2 + bj) * 8 + brow;
                ldsm4(wh4[jp], bb + 16384 + sw8(row, kk2 + bkc));
            }
            #pragma unroll
            for (int i = 0; i < 4; i++)
                #pragma unroll
                for (int j = 0; j < 4; j++)
                    mma16816(acc[i][j], ah[i], &wh4[j >> 1][(j & 1) * 2]);
        }
    }

    const int g = lane >> 2, tc = lane & 3;
    const float sc = (bn < oscale_ncols) ? oscale : 1.0f;
    #pragma unroll
    for (int i = 0; i < 4; i++) {
        #pragma unroll
        for (int j = 0; j < 4; j++) {
            const int col = bn + wn + j * 8 + tc * 2;
            const size_t r0 = (size_t)(bm + wm + i * 16 + g) * N + col;
            const size_t r1 = r0 + (size_t)8 * N;
            if (Cf) {
                float b0 = bias ? bias[col] : 0.f;
                float b1 = bias ? bias[col + 1] : 0.f;
                *(float2*)&Cf[r0] = make_float2(acc[i][j][0] + b0, acc[i][j][1] + b1);
                *(float2*)&Cf[r1] = make_float2(acc[i][j][2] + b0, acc[i][j][3] + b1);
            } else {
                *(u32*)&Oh[r0] = pack2h(acc[i][j][0] * sc, acc[i][j][1] * sc);
                *(u32*)&Oh[r1] = pack2h(acc[i][j][2] * sc, acc[i][j][3] * sc);
            }
        }
    }
}

// ---------------------------------------------------------------------------
// HMMA sp2norm attention. S in fp16 accumulators (Q pre-scaled by 1/8),
// WV in fp32 accum (R13 best config). 1-MUFU softplus (fixed). Paired-block
// loop, 4 KV ring buffers, 1 barrier per two blocks, 2 CTAs/SM.
// ---------------------------------------------------------------------------
#define AT_Q 0
#define AT_BUF 16384
#define AT_STAGE 16384
#define AT_SMEM_BYTES (16384 + 4 * AT_STAGE)

__device__ __forceinline__ void load_kv_a(
    u32 dst, int tid, const __half* __restrict__ qkv, size_t kvbase)
{
    #pragma unroll
    for (int q = 0; q < 2; q++) {
        int slot = tid + q * 256;
        int r = slot >> 3;
        int c = slot & 7;
        u32 so = sw8(r, c);
        size_t gk = kvbase + (size_t)r * (3 * CC) + CC + c * 8;
        cpa16(dst +        so, qkv + gk);        // K
        cpa16(dst + 8192 + so, qkv + gk + CC);   // V
    }
}

struct AttnState {
    float o[8][4];
    float rsq0, rsq1;
};

__device__ __forceinline__ void attn_block(
    const u32 bb, const u32 qh[4][4], AttnState& st,
    int lane, int tc, int j, int qb, int wid, int qg0)
{
    const bool dg = (j >= 2 * qb);
    if (dg && (j * 64 > qb * 128 + 16 * wid + 15)) return;

    // S = Q K^T with fp16 accumulators
    u32 s2[8][2];
    #pragma unroll
    for (int v = 0; v < 8; v++) { s2[v][0] = 0u; s2[v][1] = 0u; }

    const int rowK = (lane & 7) + ((lane >> 4) << 3);
    const int ckK  = (lane >> 3) & 1;
    #pragma unroll
    for (int t = 0; t < 4; t++) {
        #pragma unroll
        for (int u = 0; u < 4; u++) {
            int rK = 16 * u + rowK;
            u32 kh[4];
            ldsm4(kh, bb + sw8(rK, 2 * t + ckK));
            mma16816h(s2[2*u],   qh[t], kh);
            mma16816h(s2[2*u+1], qh[t], kh + 2);
        }
    }

    const int rowVb = (lane & 7) + (((lane >> 3) & 1) << 3);
    const int cvb = lane >> 4;
    #pragma unroll
    for (int t = 0; t < 4; t++) {
        float2 fa = __half22float2(*(const __half2*)&s2[2*t][0]);
        float2 fb = __half22float2(*(const __half2*)&s2[2*t][1]);
        float2 fc = __half22float2(*(const __half2*)&s2[2*t+1][0]);
        float2 fd = __half22float2(*(const __half2*)&s2[2*t+1][1]);
        float w0 = softplus_f(fa.x);
        float w1 = softplus_f(fa.y);
        float w2 = softplus_f(fb.x);
        float w3 = softplus_f(fb.y);
        float w4 = softplus_f(fc.x);
        float w5 = softplus_f(fc.y);
        float w6 = softplus_f(fd.x);
        float w7 = softplus_f(fd.y);
        if (dg) {
            int kg = j * 64 + 16 * t + 2 * tc;
            int q0 = qg0, q1 = qg0 + 8;
            if (kg     > q0) w0 = 0.f;
            if (kg + 1 > q0) w1 = 0.f;
            if (kg     > q1) w2 = 0.f;
            if (kg + 1 > q1) w3 = 0.f;
            if (kg + 8 > q0) w4 = 0.f;
            if (kg + 9 > q0) w5 = 0.f;
            if (kg + 8 > q1) w6 = 0.f;
            if (kg + 9 > q1) w7 = 0.f;
        }
        st.rsq0 = fmaf(w0, w0, st.rsq0); st.rsq0 = fmaf(w1, w1, st.rsq0);
        st.rsq0 = fmaf(w4, w4, st.rsq0); st.rsq0 = fmaf(w5, w5, st.rsq0);
        st.rsq1 = fmaf(w2, w2, st.rsq1); st.rsq1 = fmaf(w3, w3, st.rsq1);
        st.rsq1 = fmaf(w6, w6, st.rsq1); st.rsq1 = fmaf(w7, w7, st.rsq1);

        u32 wh[4];
        wh[0] = pack2h(w0, w1);
        wh[1] = pack2h(w2, w3);
        wh[2] = pack2h(w4, w5);
        wh[3] = pack2h(w6, w7);

        const int rV = 16 * t + rowVb;
        #pragma unroll
        for (int v = 0; v < 4; v++) {
            u32 vh[4];
            ldsm4t(vh, bb + 8192 + sw8(rV, 2 * v + cvb));
            mma16816(st.o[2*v],   wh, vh);
            mma16816(st.o[2*v+1], wh, vh + 2);
        }
    }
}

__global__ __launch_bounds__(256, 2)
void attn_mma(const __half* __restrict__ qkv, __half* __restrict__ att) {
    extern __shared__ char smem[];
    const u32 sb = s2u(smem);
    const int tid = threadIdx.x;
    const int wid = tid >> 5, lane = tid & 31;
    const int g = lane >> 2, tc = lane & 3;
    const int qb = gridDim.x - 1 - blockIdx.x;
    const int h = blockIdx.y, b = blockIdx.z;

    const size_t qbase = ((size_t)(b * TT + qb * 128)) * (3 * CC) + h * 64;
    const size_t kvrow = ((size_t)(b * TT)) * (3 * CC) + h * 64;

    #pragma unroll
    for (int q = 0; q < 4; q++) {
        int slot = tid + q * 256;
        int r = slot >> 3;
        int c = slot & 7;
        cpa16(sb + AT_Q + sw8(r, c), qkv + qbase + (size_t)r * (3 * CC) + c * 8);
    }
    load_kv_a(sb + AT_BUF,            tid, qkv, kvrow);
    load_kv_a(sb + AT_BUF + AT_STAGE, tid, qkv, kvrow + (size_t)64 * (3 * CC));
    CP_COMMIT();
    CP_WAIT0();
    __syncthreads();

    u32 qh[4][4];
    {
        const int row = 16 * wid + (lane & 15);
        const int ckb = lane >> 4;
        #pragma unroll
        for (int t = 0; t < 4; t++)
            ldsm4(qh[t], sb + AT_Q + sw8(row, 2 * t + ckb));
    }

    AttnState st;
    #pragma unroll
    for (int v = 0; v < 8; v++)
        #pragma unroll
        for (int u = 0; u < 4; u++) st.o[v][u] = 0.f;
    st.rsq0 = 0.f; st.rsq1 = 0.f;

    const int qg0 = qb * 128 + 16 * wid + g;
    const int jmax = 2 * qb + 1;   // odd -> even block count

    for (int jj = 0; jj <= jmax; jj += 2) {
        if (jj + 2 <= jmax) {
            load_kv_a(sb + AT_BUF + ((jj + 2) & 3) * AT_STAGE, tid, qkv,
                      kvrow + (size_t)((jj + 2) * 64) * (3 * CC));
            load_kv_a(sb + AT_BUF + ((jj + 3) & 3) * AT_STAGE, tid, qkv,
                      kvrow + (size_t)((jj + 3) * 64) * (3 * CC));
        }
        CP_COMMIT();

        attn_block(sb + AT_BUF + (jj & 3) * AT_STAGE, qh, st,
                   lane, tc, jj, qb, wid, qg0);
        attn_block(sb + AT_BUF + ((jj + 1) & 3) * AT_STAGE, qh, st,
                   lane, tc, jj + 1, qb, wid, qg0);

        CP_WAIT0();
        __syncthreads();
    }

    st.rsq0 += __shfl_xor_sync(0xffffffffu, st.rsq0, 1);
    st.rsq0 += __shfl_xor_sync(0xffffffffu, st.rsq0, 2);
    st.rsq1 += __shfl_xor_sync(0xffffffffu, st.rsq1, 1);
    st.rsq1 += __shfl_xor_sync(0xffffffffu, st.rsq1, 2);
    const float inv0 = rsqrtf(st.rsq0);
    const float inv1 = rsqrtf(st.rsq1);

    const size_t obase = (size_t)(b * TT + qg0) * CC + h * 64 + 2 * tc;
    #pragma unroll
    for (int v = 0; v < 8; v++) {
        *(u32*)&att[obase + 8 * v] = pack2h(st.o[v][0] * inv0, st.o[v][1] * inv0);
        *(u32*)&att[obase + 8 * (size_t)CC + 8 * v] =
            pack2h(st.o[v][2] * inv1, st.o[v][3] * inv1);
    }
}

// ---------------------------------------------------------------------------
extern "C" void kernel_launch(void* const* d_in, const int* in_sizes, int n_in,
                              void* d_out, int out_size) {
    const float* x     = (const float*)d_in[0];
    const float* Wqkv  = (const float*)d_in[1];
    const float* Wproj = (const float*)d_in[2];
    const float* bproj = (const float*)d_in[3];
    float* out = (float*)d_out;

    __half *xh, *wq, *wp, *qkvp, *attp;
    cudaGetSymbolAddress((void**)&xh, g_x);
    cudaGetSymbolAddress((void**)&wq, g_wq);
    cudaGetSymbolAddress((void**)&wp, g_wp);
    cudaGetSymbolAddress((void**)&qkvp, g_qkv);
    cudaGetSymbolAddress((void**)&attp, g_att);

    cudaFuncSetAttribute(gemm_mma, cudaFuncAttributeMaxDynamicSharedMemorySize,
                         GM_SMEM_BYTES);
    cudaFuncSetAttribute(attn_mma, cudaFuncAttributeMaxDynamicSharedMemorySize,
                         AT_SMEM_BYTES);

    // 0) round inputs to fp16 (single fused launch)
    round_all<<<(N4ALL + 255) / 256, 256>>>(
        (const float4*)x, (const float4*)Wqkv, (const float4*)Wproj,
        (uint2*)xh, (uint2*)wq, (uint2*)wp);

    // 1) QKV = x @ Wqkv^T -> fp16; Q columns (0..1023) pre-scaled by 1/8
    gemm_mma<<<dim3((3 * CC) / 128, BT / 128), 256, GM_SMEM_BYTES>>>(
        xh, wq, nullptr, nullptr, qkvp, 3 * CC, CC, 0.125f, CC);

    // 2) attention (causal sp2norm) -> fp16
    attn_mma<<<dim3(TT / 128, HH, BB), 256, AT_SMEM_BYTES>>>(qkvp, attp);

    // 3) out = att @ Wproj^T + b (fp32)
    gemm_mma<<<dim3(CC / 128, BT / 128), 256, GM_SMEM_BYTES>>>(
        attp, wp, bproj, out, nullptr, CC, CC, 1.0f, 0);
}

// round 17
// speedup vs baseline: 1.1299x; 1.1299x over previous
#include <cuda_runtime.h>
#include <cuda_fp16.h>
#include <math.h>

#define BB 2
#define TT 2048
#define CC 1024
#define HH 16
#define BT (BB*TT)   // 4096

typedef unsigned int u32;
typedef unsigned long long u64;

// ---------------------------------------------------------------------------
// Scratch (__device__ globals; no allocations allowed)
// ---------------------------------------------------------------------------
__device__ __align__(256) __half g_x[(size_t)BT * CC];
__device__ __align__(256) __half g_wq[(size_t)3 * CC * CC];
__device__ __align__(256) __half g_wp[(size_t)CC * CC];
__device__ __align__(256) __half g_qkv[(size_t)BT * 3 * CC];
__device__ __align__(256) __half g_att[(size_t)BT * CC];

// ---------------------------------------------------------------------------
// PTX helpers
// ---------------------------------------------------------------------------
__device__ __forceinline__ u32 s2u(const void* p) {
    u32 a;
    asm("{ .reg .u64 t; cvta.to.shared.u64 t, %1; cvt.u32.u64 %0, t; }"
        : "=r"(a) : "l"(p));
    return a;
}
__device__ __forceinline__ void cpa16(u32 dst, const void* src) {
    asm volatile("cp.async.cg.shared.global [%0], [%1], 16;" :: "r"(dst), "l"(src));
}
#define CP_COMMIT() asm volatile("cp.async.commit_group;" ::: "memory")
#define CP_WAIT0()  asm volatile("cp.async.wait_group 0;" ::: "memory")
__device__ __forceinline__ void ldsm4(u32* r, u32 addr) {
    asm volatile("ldmatrix.sync.aligned.m8n8.x4.shared.b16 {%0,%1,%2,%3}, [%4];"
                 : "=r"(r[0]), "=r"(r[1]), "=r"(r[2]), "=r"(r[3]) : "r"(addr));
}
__device__ __forceinline__ void ldsm4t(u32* r, u32 addr) {
    asm volatile("ldmatrix.sync.aligned.m8n8.x4.trans.shared.b16 {%0,%1,%2,%3}, [%4];"
                 : "=r"(r[0]), "=r"(r[1]), "=r"(r[2]), "=r"(r[3]) : "r"(addr));
}
__device__ __forceinline__ void mma16816(float* d, const u32* a, const u32* b) {
    asm volatile(
        "mma.sync.aligned.m16n8k16.row.col.f32.f16.f16.f32 "
        "{%0,%1,%2,%3}, {%4,%5,%6,%7}, {%8,%9}, {%0,%1,%2,%3};"
        : "+f"(d[0]), "+f"(d[1]), "+f"(d[2]), "+f"(d[3])
        : "r"(a[0]), "r"(a[1]), "r"(a[2]), "r"(a[3]), "r"(b[0]), "r"(b[1]));
}
// fp16-accumulate variant: D/C are two f16x2 regs {d0,d1}
__device__ __forceinline__ void mma16816h(u32* d, const u32* a, const u32* b) {
    asm volatile(
        "mma.sync.aligned.m16n8k16.row.col.f16.f16.f16.f16 "
        "{%0,%1}, {%2,%3,%4,%5}, {%6,%7}, {%0,%1};"
        : "+r"(d[0]), "+r"(d[1])
        : "r"(a[0]), "r"(a[1]), "r"(a[2]), "r"(a[3]), "r"(b[0]), "r"(b[1]));
}
__device__ __forceinline__ u32 pack2h(float a, float b) {
    u32 d;
    asm("cvt.rn.f16x2.f32 %0, %1, %2;" : "=r"(d) : "f"(b), "f"(a));
    return d;
}
// softplus via fast exp + fast log (MUFU) — R13 best-known config
__device__ __forceinline__ float softplus_f(float x) {
    float e = __expf(-fabsf(x));
    return fmaxf(x, 0.f) + __logf(1.f + e);
}

// ---------------------------------------------------------------------------
// Fused fp32 -> fp16 rounding over the three inputs (one launch)
// ---------------------------------------------------------------------------
#define N4X (BT * CC / 4)           // 1,048,576
#define N4Q (3 * CC * CC / 4)       // 786,432
#define N4P (CC * CC / 4)           // 262,144
#define N4ALL (N4X + N4Q + N4P)

__global__ __launch_bounds__(256)
void round_all(const float4* __restrict__ x, const float4* __restrict__ wq,
               const float4* __restrict__ wp, uint2* __restrict__ dx,
               uint2* __restrict__ dwq, uint2* __restrict__ dwp) {
    int i = blockIdx.x * blockDim.x + threadIdx.x;
    const float4* s; uint2* d; int k;
    if (i < N4X)            { s = x;  d = dx;  k = i; }
    else if (i < N4X + N4Q) { s = wq; d = dwq; k = i - N4X; }
    else if (i < N4ALL)     { s = wp; d = dwp; k = i - N4X - N4Q; }
    else return;
    float4 v = s[k];
    d[k] = make_uint2(pack2h(v.x, v.y), pack2h(v.z, v.w));
}

// ---------------------------------------------------------------------------
// HMMA GEMM (fp16 in, fp32 accum): C[M,N] = A[M,K] @ W[N,K]^T
// 128x128x64 tile, 8 warps (2m x 4n), double buffer, ONE sync/iter, 2 CTAs/SM.
// Oh-path epilogue scales by `oscale` when bn < oscale_ncols (Q pre-scale).
// ---------------------------------------------------------------------------
#define GM_STAGE 32768
#define GM_SMEM_BYTES (2 * GM_STAGE)

__device__ __forceinline__ u32 sw8(int r, int c) {
    return (u32)(r * 128 + ((c ^ (r & 7)) << 4));
}

__device__ __forceinline__ void load_tile_g(
    u32 sbuf, int tid,
    const __half* __restrict__ A, const __half* __restrict__ W,
    int bm, int bn, int K, int k0)
{
    #pragma unroll
    for (int q = 0; q < 4; q++) {
        int idx = tid + q * 256;
        int r = idx >> 3;
        int c = idx & 7;
        u32 so = sw8(r, c);
        cpa16(sbuf +         so, A + (size_t)(bm + r) * K + k0 + c * 8);
        cpa16(sbuf + 16384 + so, W + (size_t)(bn + r) * K + k0 + c * 8);
    }
    CP_COMMIT();
}

__global__ __launch_bounds__(256, 2)
void gemm_mma(const __half* __restrict__ A, const __half* __restrict__ W,
              const float* __restrict__ bias, float* __restrict__ Cf,
              __half* __restrict__ Oh, int N, int K,
              float oscale, int oscale_ncols) {
    extern __shared__ char smem[];
    const u32 sb = s2u(smem);
    const int tid = threadIdx.x;
    const int wid = tid >> 5, lane = tid & 31;
    const int bm = blockIdx.y * 128, bn = blockIdx.x * 128;
    const int wm = (wid >> 2) * 64;
    const int wn = (wid & 3) * 32;

    float acc[4][4][4];
    #pragma unroll
    for (int i = 0; i < 4; i++)
        #pragma unroll
        for (int j = 0; j < 4; j++)
            #pragma unroll
            for (int u = 0; u < 4; u++) acc[i][j][u] = 0.f;

    const int NIT = K / 64;

    load_tile_g(sb, tid, A, W, bm, bn, K, 0);

    const int arow = lane & 15;
    const int akh  = lane >> 4;
    const int bj   = (lane >> 4) & 1;
    const int bkc  = (lane >> 3) & 1;
    const int brow = lane & 7;

    for (int it = 0; it < NIT; it++) {
        CP_WAIT0();
        __syncthreads();
        if (it + 1 < NIT) {
            load_tile_g(sb + ((it + 1) & 1) * GM_STAGE, tid,
                        A, W, bm, bn, K, (it + 1) * 64);
        }

        const u32 bb = sb + (it & 1) * GM_STAGE;
        #pragma unroll
        for (int kk2 = 0; kk2 < 8; kk2 += 2) {
            u32 ah[4][4];
            #pragma unroll
            for (int i = 0; i < 4; i++) {
                int row = wm + i * 16 + arow;
                ldsm4(ah[i], bb + sw8(row, kk2 + akh));
            }
            u32 wh4[2][4];
            #pragma unroll
            for (int jp = 0; jp < 2; jp++) {
                int row = wn + (jp * 2 + bj) * 8 + brow;
                ldsm4(wh4[jp], bb + 16384 + sw8(row, kk2 + bkc));
            }
            #pragma unroll
            for (int i = 0; i < 4; i++)
                #pragma unroll
                for (int j = 0; j < 4; j++)
                    mma16816(acc[i][j], ah[i], &wh4[j >> 1][(j & 1) * 2]);
        }
    }

    const int g = lane >> 2, tc = lane & 3;
    const float sc = (bn < oscale_ncols) ? oscale : 1.0f;
    #pragma unroll
    for (int i = 0; i < 4; i++) {
        #pragma unroll
        for (int j = 0; j < 4; j++) {
            const int col = bn + wn + j * 8 + tc * 2;
            const size_t r0 = (size_t)(bm + wm + i * 16 + g) * N + col;
            const size_t r1 = r0 + (size_t)8 * N;
            if (Cf) {
                float b0 = bias ? bias[col] : 0.f;
                float b1 = bias ? bias[col + 1] : 0.f;
                *(float2*)&Cf[r0] = make_float2(acc[i][j][0] + b0, acc[i][j][1] + b1);
                *(float2*)&Cf[r1] = make_float2(acc[i][j][2] + b0, acc[i][j][3] + b1);
            } else {
                *(u32*)&Oh[r0] = pack2h(acc[i][j][0] * sc, acc[i][j][1] * sc);
                *(u32*)&Oh[r1] = pack2h(acc[i][j][2] * sc, acc[i][j][3] * sc);
            }
        }
    }
}

// ---------------------------------------------------------------------------
// HMMA sp2norm attention. S in fp16 accumulators (Q pre-scaled by 1/8),
// WV in fp32 accum. 2-MUFU softplus. Paired-block loop, 4 KV ring buffers,
// 1 barrier per two blocks, 2 CTAs/SM.  (R13 best-known configuration.)
// ---------------------------------------------------------------------------
#define AT_Q 0
#define AT_BUF 16384
#define AT_STAGE 16384
#define AT_SMEM_BYTES (16384 + 4 * AT_STAGE)

__device__ __forceinline__ void load_kv_a(
    u32 dst, int tid, const __half* __restrict__ qkv, size_t kvbase)
{
    #pragma unroll
    for (int q = 0; q < 2; q++) {
        int slot = tid + q * 256;
        int r = slot >> 3;
        int c = slot & 7;
        u32 so = sw8(r, c);
        size_t gk = kvbase + (size_t)r * (3 * CC) + CC + c * 8;
        cpa16(dst +        so, qkv + gk);        // K
        cpa16(dst + 8192 + so, qkv + gk + CC);   // V
    }
}

struct AttnState {
    float o[8][4];
    float rsq0, rsq1;
};

__device__ __forceinline__ void attn_block(
    const u32 bb, const u32 qh[4][4], AttnState& st,
    int lane, int tc, int j, int qb, int wid, int qg0)
{
    const bool dg = (j >= 2 * qb);
    if (dg && (j * 64 > qb * 128 + 16 * wid + 15)) return;

    // S = Q K^T with fp16 accumulators
    u32 s2[8][2];
    #pragma unroll
    for (int v = 0; v < 8; v++) { s2[v][0] = 0u; s2[v][1] = 0u; }

    const int rowK = (lane & 7) + ((lane >> 4) << 3);
    const int ckK  = (lane >> 3) & 1;
    #pragma unroll
    for (int t = 0; t < 4; t++) {
        #pragma unroll
        for (int u = 0; u < 4; u++) {
            int rK = 16 * u + rowK;
            u32 kh[4];
            ldsm4(kh, bb + sw8(rK, 2 * t + ckK));
            mma16816h(s2[2*u],   qh[t], kh);
            mma16816h(s2[2*u+1], qh[t], kh + 2);
        }
    }

    const int rowVb = (lane & 7) + (((lane >> 3) & 1) << 3);
    const int cvb = lane >> 4;
    #pragma unroll
    for (int t = 0; t < 4; t++) {
        float2 fa = __half22float2(*(const __half2*)&s2[2*t][0]);
        float2 fb = __half22float2(*(const __half2*)&s2[2*t][1]);
        float2 fc = __half22float2(*(const __half2*)&s2[2*t+1][0]);
        float2 fd = __half22float2(*(const __half2*)&s2[2*t+1][1]);
        float w0 = softplus_f(fa.x);
        float w1 = softplus_f(fa.y);
        float w2 = softplus_f(fb.x);
        float w3 = softplus_f(fb.y);
        float w4 = softplus_f(fc.x);
        float w5 = softplus_f(fc.y);
        float w6 = softplus_f(fd.x);
        float w7 = softplus_f(fd.y);
        if (dg) {
            int kg = j * 64 + 16 * t + 2 * tc;
            int q0 = qg0, q1 = qg0 + 8;
            if (kg     > q0) w0 = 0.f;
            if (kg + 1 > q0) w1 = 0.f;
            if (kg     > q1) w2 = 0.f;
            if (kg + 1 > q1) w3 = 0.f;
            if (kg + 8 > q0) w4 = 0.f;
            if (kg + 9 > q0) w5 = 0.f;
            if (kg + 8 > q1) w6 = 0.f;
            if (kg + 9 > q1) w7 = 0.f;
        }
        st.rsq0 = fmaf(w0, w0, st.rsq0); st.rsq0 = fmaf(w1, w1, st.rsq0);
        st.rsq0 = fmaf(w4, w4, st.rsq0); st.rsq0 = fmaf(w5, w5, st.rsq0);
        st.rsq1 = fmaf(w2, w2, st.rsq1); st.rsq1 = fmaf(w3, w3, st.rsq1);
        st.rsq1 = fmaf(w6, w6, st.rsq1); st.rsq1 = fmaf(w7, w7, st.rsq1);

        u32 wh[4];
        wh[0] = pack2h(w0, w1);
        wh[1] = pack2h(w2, w3);
        wh[2] = pack2h(w4, w5);
        wh[3] = pack2h(w6, w7);

        const int rV = 16 * t + rowVb;
        #pragma unroll
        for (int v = 0; v < 4; v++) {
            u32 vh[4];
            ldsm4t(vh, bb + 8192 + sw8(rV, 2 * v + cvb));
            mma16816(st.o[2*v],   wh, vh);
            mma16816(st.o[2*v+1], wh, vh + 2);
        }
    }
}

__global__ __launch_bounds__(256, 2)
void attn_mma(const __half* __restrict__ qkv, __half* __restrict__ att) {
    extern __shared__ char smem[];
    const u32 sb = s2u(smem);
    const int tid = threadIdx.x;
    const int wid = tid >> 5, lane = tid & 31;
    const int g = lane >> 2, tc = lane & 3;
    const int qb = gridDim.x - 1 - blockIdx.x;
    const int h = blockIdx.y, b = blockIdx.z;

    const size_t qbase = ((size_t)(b * TT + qb * 128)) * (3 * CC) + h * 64;
    const size_t kvrow = ((size_t)(b * TT)) * (3 * CC) + h * 64;

    #pragma unroll
    for (int q = 0; q < 4; q++) {
        int slot = tid + q * 256;
        int r = slot >> 3;
        int c = slot & 7;
        cpa16(sb + AT_Q + sw8(r, c), qkv + qbase + (size_t)r * (3 * CC) + c * 8);
    }
    load_kv_a(sb + AT_BUF,            tid, qkv, kvrow);
    load_kv_a(sb + AT_BUF + AT_STAGE, tid, qkv, kvrow + (size_t)64 * (3 * CC));
    CP_COMMIT();
    CP_WAIT0();
    __syncthreads();

    u32 qh[4][4];
    {
        const int row = 16 * wid + (lane & 15);
        const int ckb = lane >> 4;
        #pragma unroll
        for (int t = 0; t < 4; t++)
            ldsm4(qh[t], sb + AT_Q + sw8(row, 2 * t + ckb));
    }

    AttnState st;
    #pragma unroll
    for (int v = 0; v < 8; v++)
        #pragma unroll
        for (int u = 0; u < 4; u++) st.o[v][u] = 0.f;
    st.rsq0 = 0.f; st.rsq1 = 0.f;

    const int qg0 = qb * 128 + 16 * wid + g;
    const int jmax = 2 * qb + 1;   // odd -> even block count

    for (int jj = 0; jj <= jmax; jj += 2) {
        if (jj + 2 <= jmax) {
            load_kv_a(sb + AT_BUF + ((jj + 2) & 3) * AT_STAGE, tid, qkv,
                      kvrow + (size_t)((jj + 2) * 64) * (3 * CC));
            load_kv_a(sb + AT_BUF + ((jj + 3) & 3) * AT_STAGE, tid, qkv,
                      kvrow + (size_t)((jj + 3) * 64) * (3 * CC));
        }
        CP_COMMIT();

        attn_block(sb + AT_BUF + (jj & 3) * AT_STAGE, qh, st,
                   lane, tc, jj, qb, wid, qg0);
        attn_block(sb + AT_BUF + ((jj + 1) & 3) * AT_STAGE, qh, st,
                   lane, tc, jj + 1, qb, wid, qg0);

        CP_WAIT0();
        __syncthreads();
    }

    st.rsq0 += __shfl_xor_sync(0xffffffffu, st.rsq0, 1);
    st.rsq0 += __shfl_xor_sync(0xffffffffu, st.rsq0, 2);
    st.rsq1 += __shfl_xor_sync(0xffffffffu, st.rsq1, 1);
    st.rsq1 += __shfl_xor_sync(0xffffffffu, st.rsq1, 2);
    const float inv0 = rsqrtf(st.rsq0);
    const float inv1 = rsqrtf(st.rsq1);

    const size_t obase = (size_t)(b * TT + qg0) * CC + h * 64 + 2 * tc;
    #pragma unroll
    for (int v = 0; v < 8; v++) {
        *(u32*)&att[obase + 8 * v] = pack2h(st.o[v][0] * inv0, st.o[v][1] * inv0);
        *(u32*)&att[obase + 8 * (size_t)CC + 8 * v] =
            pack2h(st.o[v][2] * inv1, st.o[v][3] * inv1);
    }
}

// ---------------------------------------------------------------------------
extern "C" void kernel_launch(void* const* d_in, const int* in_sizes, int n_in,
                              void* d_out, int out_size) {
    const float* x     = (const float*)d_in[0];
    const float* Wqkv  = (const float*)d_in[1];
    const float* Wproj = (const float*)d_in[2];
    const float* bproj = (const float*)d_in[3];
    float* out = (float*)d_out;

    __half *xh, *wq, *wp, *qkvp, *attp;
    cudaGetSymbolAddress((void**)&xh, g_x);
    cudaGetSymbolAddress((void**)&wq, g_wq);
    cudaGetSymbolAddress((void**)&wp, g_wp);
    cudaGetSymbolAddress((void**)&qkvp, g_qkv);
    cudaGetSymbolAddress((void**)&attp, g_att);

    cudaFuncSetAttribute(gemm_mma, cudaFuncAttributeMaxDynamicSharedMemorySize,
                         GM_SMEM_BYTES);
    cudaFuncSetAttribute(attn_mma, cudaFuncAttributeMaxDynamicSharedMemorySize,
                         AT_SMEM_BYTES);

    // 0) round inputs to fp16 (single fused launch)
    round_all<<<(N4ALL + 255) / 256, 256>>>(
        (const float4*)x, (const float4*)Wqkv, (const float4*)Wproj,
        (uint2*)xh, (uint2*)wq, (uint2*)wp);

    // 1) QKV = x @ Wqkv^T -> fp16; Q columns (0..1023) pre-scaled by 1/8
    gemm_mma<<<dim3((3 * CC) / 128, BT / 128), 256, GM_SMEM_BYTES>>>(
        xh, wq, nullptr, nullptr, qkvp, 3 * CC, CC, 0.125f, CC);

    // 2) attention (causal sp2norm) -> fp16
    attn_mma<<<dim3(TT / 128, HH, BB), 256, AT_SMEM_BYTES>>>(qkvp, attp);

    // 3) out = att @ Wproj^T + b (fp32)
    gemm_mma<<<dim3(CC / 128, BT / 128), 256, GM_SMEM_BYTES>>>(
        attp, wp, bproj, out, nullptr, CC, CC, 1.0f, 0);
}